// round 16
// baseline (speedup 1.0000x reference)
#include <cuda_runtime.h>
#include <math.h>

#define R 32
#define PB 36              /* padded smem row stride */
#define L 2048
#define NSEQ 8192
#define NL (NSEQ * L)
#define NL4 (NL / 4)       /* 4194304 */
#define L4 (L / 4)         /* 512     */

#define CSPLIT 48          /* t < 192 -> B path */

#define THREADS 256
#define B_BLOCKS 192
#define A_BLOCKS 512
#define A_ITEMS 32         /* 512*256*32 = NL4 */
#define A_STRIDE (A_BLOCKS * THREADS)   /* 131072, multiple of L4 */
#define TOTAL_BLOCKS (B_BLOCKS + A_BLOCKS)   /* 704 */
#define DEPTH 8            /* cp.async pipeline depth (16B/thread/stage) */

__device__ float    g_A2t[R][L];
__device__ float    g_B2t[R][L];
__device__ float    g_C2[R];
__device__ float    g_D[R];
__device__ int      g_Kt4[L4];
__device__ float    g_partial[TOTAL_BLOCKS];
__device__ unsigned g_count;

__device__ __forceinline__ float ex2f(float x) {
    float y; asm("ex2.approx.f32 %0, %1;" : "=f"(y) : "f"(x)); return y;
}
__device__ __forceinline__ float lg2f_(float x) {
    float y; asm("lg2.approx.f32 %0, %1;" : "=f"(y) : "f"(x)); return y;
}

#define LN2_F 0.69314718055994531f
#define INV_LN2_F 1.44269504088896340f
#define HALF_LOG_2PI 0.91893853320467274f
#define DROP_THRESH (-18.0f)
#define XLO (-8.0f)
#define XHI (8.0f)

// ---------------------------------------------------------------------------
// k_prep: proven. 128 blocks x 256 threads; block b emits tables for t in
// [16b,16b+16). h_t == stationary pi for t >= 64 (Doeblin ~0.5).
// ---------------------------------------------------------------------------
__global__ void __launch_bounds__(256) k_prep(const float* __restrict__ Tr,
                                              const float* __restrict__ init_w,
                                              const float* __restrict__ sig,
                                              const float* __restrict__ mu_rates) {
    __shared__ float P[6][R][PB];
    __shared__ float hs[8][R];
    __shared__ float pi_s[R];
    __shared__ int   karr[8];
    const int tid  = threadIdx.x;
    const int w    = tid >> 5, lane = tid & 31;
    const int rw   = tid >> 3, seg = (tid & 7) * 4;
    const int b    = blockIdx.x;

    if (b == 0 && tid == 0) g_count = 0u;

    *(float4*)&P[0][rw][seg] = ((const float4*)Tr)[tid];
    __syncthreads();

    #pragma unroll 1
    for (int k = 1; k < 6; ++k) {
        float4 a0 = make_float4(0.f, 0.f, 0.f, 0.f);
        float4 a1 = make_float4(0.f, 0.f, 0.f, 0.f);
        #pragma unroll
        for (int j = 0; j < R; j += 2) {
            float  r0 = P[k - 1][rw][j];
            float4 b0 = *(const float4*)&P[k - 1][j][seg];
            a0.x = fmaf(r0, b0.x, a0.x); a0.y = fmaf(r0, b0.y, a0.y);
            a0.z = fmaf(r0, b0.z, a0.z); a0.w = fmaf(r0, b0.w, a0.w);
            float  r1 = P[k - 1][rw][j + 1];
            float4 b1 = *(const float4*)&P[k - 1][j + 1][seg];
            a1.x = fmaf(r1, b1.x, a1.x); a1.y = fmaf(r1, b1.y, a1.y);
            a1.z = fmaf(r1, b1.z, a1.z); a1.w = fmaf(r1, b1.w, a1.w);
        }
        float4 acc = make_float4(a0.x + a1.x, a0.y + a1.y, a0.z + a1.z, a0.w + a1.w);
        *(float4*)&P[k][rw][seg] = acc;
        __syncthreads();
    }

    if (w == 0) {
        hs[0][lane] = init_w[lane];
        __syncwarp();
        #pragma unroll 1
        for (int rep = 0; rep < 2; ++rep) {
            float a0 = 0.f, a1 = 0.f, a2 = 0.f, a3 = 0.f;
            #pragma unroll
            for (int j = 0; j < R; j += 4) {
                a0 = fmaf(hs[0][j    ], P[5][j    ][lane], a0);
                a1 = fmaf(hs[0][j + 1], P[5][j + 1][lane], a1);
                a2 = fmaf(hs[0][j + 2], P[5][j + 2][lane], a2);
                a3 = fmaf(hs[0][j + 3], P[5][j + 3][lane], a3);
            }
            float v = (a0 + a1) + (a2 + a3);
            __syncwarp();
            hs[0][lane] = v;
            __syncwarp();
        }
        pi_s[lane] = hs[0][lane];
    }
    __syncthreads();

    float sg     = sig[lane];
    float inv_s2 = 1.0f / (sg * sg);
    float l2sig  = lg2f_(sg);
    float mr     = mu_rates[lane];
    float C2     = -0.5f * inv_s2 * INV_LN2_F;
    if (b == 0 && w == 0) {
        g_C2[lane] = C2;
        g_D[lane]  = mr * inv_s2 * INV_LN2_F;
    }

    int kloc = 1;
    #pragma unroll 1
    for (int i = 0; i < 2; ++i) {
        int t = b * 16 + w * 2 + i;
        if (t < 64) {
            hs[w][lane] = init_w[lane];
            __syncwarp();
            #pragma unroll 1
            for (int k = 0; k < 6; ++k) {
                if ((t >> k) & 1) {
                    float a0 = 0.f, a1 = 0.f, a2 = 0.f, a3 = 0.f;
                    #pragma unroll
                    for (int j = 0; j < R; j += 4) {
                        a0 = fmaf(hs[w][j    ], P[k][j    ][lane], a0);
                        a1 = fmaf(hs[w][j + 1], P[k][j + 1][lane], a1);
                        a2 = fmaf(hs[w][j + 2], P[k][j + 2][lane], a2);
                        a3 = fmaf(hs[w][j + 3], P[k][j + 3][lane], a3);
                    }
                    float v = (a0 + a1) + (a2 + a3);
                    __syncwarp();
                    hs[w][lane] = v;
                    __syncwarp();
                }
            }
        } else {
            hs[w][lane] = pi_s[lane];
            __syncwarp();
        }

        float sum = 0.0f;
        #pragma unroll
        for (int j = 0; j < R; ++j) sum += hs[w][j];
        float lm2 = lg2f_(hs[w][lane]) - lg2f_(sum);

        float mu = (float)t * mr;
        float B2 = mu * inv_s2 * INV_LN2_F;
        float A2 = lm2 - l2sig - 0.5f * mu * mu * inv_s2 * INV_LN2_F;
        g_A2t[lane][t] = A2;
        g_B2t[lane][t] = B2;

        float A0 = __shfl_sync(0xffffffffu, A2, 0);
        float B0 = __shfl_sync(0xffffffffu, B2, 0);
        float C0 = __shfl_sync(0xffffffffu, C2, 0);
        float dA = A2 - A0, dB = B2 - B0, dC = C2 - C0;
        float d1 = dA + dB * XLO + dC * XLO * XLO;
        float d2 = dA + dB * XHI + dC * XHI * XHI;
        float dmax = fmaxf(d1, d2);
        if (fabsf(dC) > 1e-20f) {
            float xv = -dB / (2.0f * dC);
            if (xv > XLO && xv < XHI) dmax = fmaxf(dmax, dA + dB * xv + dC * xv * xv);
        }
        bool keep = (dmax >= DROP_THRESH);
        unsigned bm = __ballot_sync(0xffffffffu, keep);
        int K = 32 - __clz(bm);
        kloc = max(kloc, K);
    }
    if (lane == 0) karr[w] = kloc;
    __syncthreads();
    if (tid < 4)
        g_Kt4[b * 4 + tid] = max(karr[2 * tid], karr[2 * tid + 1]);
}

// ---------------------------------------------------------------------------
// Robust per-element logsumexp (cold fallbacks only)
// ---------------------------------------------------------------------------
__device__ __noinline__ float robust_lp(float x, float q, int t, int K) {
    float m = -3.0e38f;
    for (int r = 0; r < K; ++r) {
        float arg = fmaf(g_C2[r], q, fmaf(g_B2t[r][t], x, g_A2t[r][t]));
        m = fmaxf(m, arg);
    }
    float s = 0.0f;
    for (int r = 0; r < K; ++r) {
        float arg = fmaf(g_C2[r], q, fmaf(g_B2t[r][t], x, g_A2t[r][t]));
        s += ex2f(arg - m);
    }
    return LN2_F * (m + lg2f_(s));
}

// Cold A handler (provably unreachable for c>=48; kept for safety).
__device__ __noinline__ float coldA(const float4* __restrict__ X4,
                                    int tid, int c, int K) {
    float acc = 0.0f;
    for (int k = 0; k < A_ITEMS; ++k) {
        float4 xv = X4[tid + k * A_STRIDE];
        int t0 = c * 4;
        acc += robust_lp(xv.x, xv.x * xv.x, t0,     K);
        acc += robust_lp(xv.y, xv.y * xv.y, t0 + 1, K);
        acc += robust_lp(xv.z, xv.z * xv.z, t0 + 2, K);
        acc += robust_lp(xv.w, xv.w * xv.w, t0 + 3, K);
    }
    return acc - (float)(4 * A_ITEMS) * HALF_LOG_2PI;
}

// ---------------------------------------------------------------------------
// Fused main. Blocks [0,192): B path (t<192), c-coherent warps, balanced
// interleave, MUFU ex2. Blocks [192,704): A path — cp.async (LDGSTS) 8-deep
// per-thread pipeline into a 32KB smem ring: in-flight bytes live in SMEM,
// not the register file, so per-SM outstanding traffic (~200KB) far exceeds
// the bandwidth-delay product while regs stay lean. Strided coalesced layout,
// c = tid & 511 constant per thread. Deterministic fixed-order tail.
// ---------------------------------------------------------------------------
__global__ void __launch_bounds__(THREADS) k_main(const float* __restrict__ X,
                                                  float* __restrict__ out) {
    __shared__ __align__(16) char sraw[DEPTH * THREADS * 16];   /* 32KB union */
    __shared__ float  sD[R], sC[R];
    __shared__ int    sK[CSPLIT];
    __shared__ float  sred[THREADS];
    __shared__ bool   s_last;

    const float4* X4 = (const float4*)X;
    const float4* A4 = (const float4*)g_A2t;
    const int th = threadIdx.x;
    float acc = 0.0f;

    if (blockIdx.x < B_BLOCKS) {
        // ---------------- B path: t < 192 ----------------
        float4 (*sA)[CSPLIT] = (float4 (*)[CSPLIT])sraw;        /* 24.5KB */
        #pragma unroll
        for (int j = 0; j < (R * CSPLIT + THREADS - 1) / THREADS; ++j) {
            int e = th + j * THREADS;
            if (e < R * CSPLIT) {
                int r = e / CSPLIT, c = e - r * CSPLIT;
                sA[r][c] = A4[r * L4 + c];
            }
        }
        if (th < R) { sD[th] = g_D[th]; sC[th] = g_C2[th]; }
        if (th < CSPLIT) sK[th] = g_Kt4[th];
        __syncthreads();

        const int lane = th & 31;
        const int W = blockIdx.x * 8 + (th >> 5);
        const int idx = W % CSPLIT;
        const int c = (idx & 1) ? (CSPLIT - 1 - (idx >> 1)) : (idx >> 1);
        const int ng = W / CSPLIT;

        float4 xv[8];
        #pragma unroll
        for (int it = 0; it < 8; ++it) {
            int n = ng * 256 + it * 32 + lane;
            xv[it] = __ldcs(&X4[n * L4 + c]);
        }

        const int K = sK[c];
        const float t0f = (float)(4 * c);

        #pragma unroll 1
        for (int it = 0; it < 8; ++it) {
            float x0 = xv[it].x, x1 = xv[it].y, x2 = xv[it].z, x3 = xv[it].w;
            float q0 = x0 * x0, q1 = x1 * x1, q2 = x2 * x2, q3 = x3 * x3;
            float S0 = 0.f, S1 = 0.f, S2 = 0.f, S3 = 0.f;
            #pragma unroll 2
            for (int r = 0; r < K; ++r) {
                float4 ar = sA[r][c];
                float d  = sD[r];
                float cr = sC[r];
                float b0 = d * t0f, b1 = b0 + d, b2 = b1 + d, b3 = b2 + d;
                S0 += ex2f(fmaf(cr, q0, fmaf(b0, x0, ar.x)));
                S1 += ex2f(fmaf(cr, q1, fmaf(b1, x1, ar.y)));
                S2 += ex2f(fmaf(cr, q2, fmaf(b2, x2, ar.z)));
                S3 += ex2f(fmaf(cr, q3, fmaf(b3, x3, ar.w)));
            }
            float smin = fminf(fminf(S0, S1), fminf(S2, S3));
            if (smin > 1e-30f) {
                acc += LN2_F * (lg2f_(S0) + lg2f_(S1) + lg2f_(S2) + lg2f_(S3));
            } else {
                int tt = c * 4;
                acc += robust_lp(x0, q0, tt,     K);
                acc += robust_lp(x1, q1, tt + 1, K);
                acc += robust_lp(x2, q2, tt + 2, K);
                acc += robust_lp(x3, q3, tt + 3, K);
            }
            acc -= 4.0f * HALF_LOG_2PI;
        }
    } else {
        // ---------------- A path: cp.async pipelined streaming ----------------
        const float4* B4 = (const float4*)g_B2t;
        const int tid = (blockIdx.x - B_BLOCKS) * THREADS + th;   // 0..131071
        const int c = tid & (L4 - 1);
        float4 (*sbuf)[THREADS] = (float4 (*)[THREADS])sraw;

        if (c >= CSPLIT) {
            const int K = g_Kt4[c];
            if (K != 1) {
                acc = coldA(X4, tid, c, K);   // unreachable safety path
            } else {
                const float4 a = A4[c];
                const float4 b = B4[c];
                const float cc = g_C2[0];
                unsigned sb = (unsigned)__cvta_generic_to_shared(&sbuf[0][th]);
                const unsigned sstep = THREADS * 16;

                #pragma unroll
                for (int k = 0; k < DEPTH; ++k) {
                    asm volatile("cp.async.cg.shared.global [%0], [%1], 16;"
                                 :: "r"(sb + k * sstep),
                                    "l"(&X4[tid + k * A_STRIDE]) : "memory");
                    asm volatile("cp.async.commit_group;" ::: "memory");
                }

                float s = 0.0f;
                #pragma unroll 1
                for (int k = 0; k < A_ITEMS; ++k) {
                    asm volatile("cp.async.wait_group %0;" :: "n"(DEPTH - 1) : "memory");
                    float4 xv = sbuf[k & (DEPTH - 1)][th];
                    int nk = k + DEPTH;
                    if (nk < A_ITEMS) {
                        asm volatile("cp.async.cg.shared.global [%0], [%1], 16;"
                                     :: "r"(sb + (k & (DEPTH - 1)) * sstep),
                                        "l"(&X4[tid + nk * A_STRIDE]) : "memory");
                    }
                    asm volatile("cp.async.commit_group;" ::: "memory");

                    float x0 = xv.x, x1 = xv.y, x2 = xv.z, x3 = xv.w;
                    float g0 = fmaf(cc, x0 * x0, fmaf(b.x, x0, a.x));
                    float g1 = fmaf(cc, x1 * x1, fmaf(b.y, x1, a.y));
                    float g2 = fmaf(cc, x2 * x2, fmaf(b.z, x2, a.z));
                    float g3 = fmaf(cc, x3 * x3, fmaf(b.w, x3, a.w));
                    s += (g0 + g1) + (g2 + g3);
                }
                acc = LN2_F * s - (float)(4 * A_ITEMS) * HALF_LOG_2PI;
            }
        }
        __syncthreads();   // uniform per block before smem reuse in tail
    }

    // ---------------- fused deterministic tail ----------------
    sred[th] = acc;
    __syncthreads();
    for (int s = THREADS / 2; s > 0; s >>= 1) {
        if (th < s) sred[th] += sred[th + s];
        __syncthreads();
    }
    if (th == 0) {
        g_partial[blockIdx.x] = sred[0];
        __threadfence();
        unsigned n = atomicAdd(&g_count, 1u);
        s_last = (n == TOTAL_BLOCKS - 1);
    }
    __syncthreads();

    if (s_last) {
        __threadfence();
        float v = 0.0f;
        for (int idx = th; idx < TOTAL_BLOCKS; idx += THREADS)
            v += g_partial[idx];
        sred[th] = v;
        __syncthreads();
        for (int s = THREADS / 2; s > 0; s >>= 1) {
            if (th < s) sred[th] += sred[th + s];
            __syncthreads();
        }
        if (th == 0) out[0] = sred[0] / (float)NSEQ;
    }
}

// ---------------------------------------------------------------------------
extern "C" void kernel_launch(void* const* d_in, const int* in_sizes, int n_in,
                              void* d_out, int out_size) {
    const float* X       = (const float*)d_in[0];
    const float* Tr      = (const float*)d_in[1];
    const float* init_w  = (const float*)d_in[2];
    const float* sig     = (const float*)d_in[3];
    const float* mu_rate = (const float*)d_in[4];
    float* out = (float*)d_out;

    k_prep<<<128, 256>>>(Tr, init_w, sig, mu_rate);
    k_main<<<TOTAL_BLOCKS, THREADS>>>(X, out);
}

// round 17
// speedup vs baseline: 1.0182x; 1.0182x over previous
#include <cuda_runtime.h>
#include <math.h>

#define R 32
#define PB 36              /* padded smem row stride */
#define L 2048
#define NSEQ 8192
#define NL (NSEQ * L)
#define NL4 (NL / 4)       /* 4194304 */
#define L4 (L / 4)         /* 512     */

#define CSPLIT 48          /* t < 192 -> B path */

#define THREADS 256
#define B_BLOCKS 192
#define A_BLOCKS 512
#define A_ITEMS 32         /* 512*256*32 = NL4 */
#define A_STRIDE (A_BLOCKS * THREADS)   /* 131072, multiple of L4 */
#define TOTAL_BLOCKS (B_BLOCKS + A_BLOCKS)   /* 704 */
#define DEPTH 8            /* cp.async pipeline depth (16B/thread/stage) */

__device__ float    g_A2t[R][L];
__device__ float    g_B2t[R][L];
__device__ float    g_C2[R];
__device__ float    g_D[R];
__device__ int      g_Kt4[L4];
__device__ float    g_partial[TOTAL_BLOCKS];
__device__ unsigned g_count;

__device__ __forceinline__ float ex2f(float x) {
    float y; asm("ex2.approx.f32 %0, %1;" : "=f"(y) : "f"(x)); return y;
}
__device__ __forceinline__ float lg2f_(float x) {
    float y; asm("lg2.approx.f32 %0, %1;" : "=f"(y) : "f"(x)); return y;
}

#define LN2_F 0.69314718055994531f
#define INV_LN2_F 1.44269504088896340f
#define HALF_LOG_2PI 0.91893853320467274f
#define DROP_THRESH (-18.0f)
#define XLO (-8.0f)
#define XHI (8.0f)

// ---------------------------------------------------------------------------
// k_prep: proven. 128 blocks x 256 threads; block b emits tables for t in
// [16b,16b+16). h_t == stationary pi for t >= 64 (Doeblin ~0.5).
// ---------------------------------------------------------------------------
__global__ void __launch_bounds__(256) k_prep(const float* __restrict__ Tr,
                                              const float* __restrict__ init_w,
                                              const float* __restrict__ sig,
                                              const float* __restrict__ mu_rates) {
    __shared__ float P[6][R][PB];
    __shared__ float hs[8][R];
    __shared__ float pi_s[R];
    __shared__ int   karr[8];
    const int tid  = threadIdx.x;
    const int w    = tid >> 5, lane = tid & 31;
    const int rw   = tid >> 3, seg = (tid & 7) * 4;
    const int b    = blockIdx.x;

    if (b == 0 && tid == 0) g_count = 0u;

    *(float4*)&P[0][rw][seg] = ((const float4*)Tr)[tid];
    __syncthreads();

    #pragma unroll 1
    for (int k = 1; k < 6; ++k) {
        float4 a0 = make_float4(0.f, 0.f, 0.f, 0.f);
        float4 a1 = make_float4(0.f, 0.f, 0.f, 0.f);
        #pragma unroll
        for (int j = 0; j < R; j += 2) {
            float  r0 = P[k - 1][rw][j];
            float4 b0 = *(const float4*)&P[k - 1][j][seg];
            a0.x = fmaf(r0, b0.x, a0.x); a0.y = fmaf(r0, b0.y, a0.y);
            a0.z = fmaf(r0, b0.z, a0.z); a0.w = fmaf(r0, b0.w, a0.w);
            float  r1 = P[k - 1][rw][j + 1];
            float4 b1 = *(const float4*)&P[k - 1][j + 1][seg];
            a1.x = fmaf(r1, b1.x, a1.x); a1.y = fmaf(r1, b1.y, a1.y);
            a1.z = fmaf(r1, b1.z, a1.z); a1.w = fmaf(r1, b1.w, a1.w);
        }
        float4 acc = make_float4(a0.x + a1.x, a0.y + a1.y, a0.z + a1.z, a0.w + a1.w);
        *(float4*)&P[k][rw][seg] = acc;
        __syncthreads();
    }

    if (w == 0) {
        hs[0][lane] = init_w[lane];
        __syncwarp();
        #pragma unroll 1
        for (int rep = 0; rep < 2; ++rep) {
            float a0 = 0.f, a1 = 0.f, a2 = 0.f, a3 = 0.f;
            #pragma unroll
            for (int j = 0; j < R; j += 4) {
                a0 = fmaf(hs[0][j    ], P[5][j    ][lane], a0);
                a1 = fmaf(hs[0][j + 1], P[5][j + 1][lane], a1);
                a2 = fmaf(hs[0][j + 2], P[5][j + 2][lane], a2);
                a3 = fmaf(hs[0][j + 3], P[5][j + 3][lane], a3);
            }
            float v = (a0 + a1) + (a2 + a3);
            __syncwarp();
            hs[0][lane] = v;
            __syncwarp();
        }
        pi_s[lane] = hs[0][lane];
    }
    __syncthreads();

    float sg     = sig[lane];
    float inv_s2 = 1.0f / (sg * sg);
    float l2sig  = lg2f_(sg);
    float mr     = mu_rates[lane];
    float C2     = -0.5f * inv_s2 * INV_LN2_F;
    if (b == 0 && w == 0) {
        g_C2[lane] = C2;
        g_D[lane]  = mr * inv_s2 * INV_LN2_F;
    }

    int kloc = 1;
    #pragma unroll 1
    for (int i = 0; i < 2; ++i) {
        int t = b * 16 + w * 2 + i;
        if (t < 64) {
            hs[w][lane] = init_w[lane];
            __syncwarp();
            #pragma unroll 1
            for (int k = 0; k < 6; ++k) {
                if ((t >> k) & 1) {
                    float a0 = 0.f, a1 = 0.f, a2 = 0.f, a3 = 0.f;
                    #pragma unroll
                    for (int j = 0; j < R; j += 4) {
                        a0 = fmaf(hs[w][j    ], P[k][j    ][lane], a0);
                        a1 = fmaf(hs[w][j + 1], P[k][j + 1][lane], a1);
                        a2 = fmaf(hs[w][j + 2], P[k][j + 2][lane], a2);
                        a3 = fmaf(hs[w][j + 3], P[k][j + 3][lane], a3);
                    }
                    float v = (a0 + a1) + (a2 + a3);
                    __syncwarp();
                    hs[w][lane] = v;
                    __syncwarp();
                }
            }
        } else {
            hs[w][lane] = pi_s[lane];
            __syncwarp();
        }

        float sum = 0.0f;
        #pragma unroll
        for (int j = 0; j < R; ++j) sum += hs[w][j];
        float lm2 = lg2f_(hs[w][lane]) - lg2f_(sum);

        float mu = (float)t * mr;
        float B2 = mu * inv_s2 * INV_LN2_F;
        float A2 = lm2 - l2sig - 0.5f * mu * mu * inv_s2 * INV_LN2_F;
        g_A2t[lane][t] = A2;
        g_B2t[lane][t] = B2;

        float A0 = __shfl_sync(0xffffffffu, A2, 0);
        float B0 = __shfl_sync(0xffffffffu, B2, 0);
        float C0 = __shfl_sync(0xffffffffu, C2, 0);
        float dA = A2 - A0, dB = B2 - B0, dC = C2 - C0;
        float d1 = dA + dB * XLO + dC * XLO * XLO;
        float d2 = dA + dB * XHI + dC * XHI * XHI;
        float dmax = fmaxf(d1, d2);
        if (fabsf(dC) > 1e-20f) {
            float xv = -dB / (2.0f * dC);
            if (xv > XLO && xv < XHI) dmax = fmaxf(dmax, dA + dB * xv + dC * xv * xv);
        }
        bool keep = (dmax >= DROP_THRESH);
        unsigned bm = __ballot_sync(0xffffffffu, keep);
        int K = 32 - __clz(bm);
        kloc = max(kloc, K);
    }
    if (lane == 0) karr[w] = kloc;
    __syncthreads();
    if (tid < 4)
        g_Kt4[b * 4 + tid] = max(karr[2 * tid], karr[2 * tid + 1]);
}

// ---------------------------------------------------------------------------
// Robust per-element logsumexp (cold fallbacks only)
// ---------------------------------------------------------------------------
__device__ __noinline__ float robust_lp(float x, float q, int t, int K) {
    float m = -3.0e38f;
    for (int r = 0; r < K; ++r) {
        float arg = fmaf(g_C2[r], q, fmaf(g_B2t[r][t], x, g_A2t[r][t]));
        m = fmaxf(m, arg);
    }
    float s = 0.0f;
    for (int r = 0; r < K; ++r) {
        float arg = fmaf(g_C2[r], q, fmaf(g_B2t[r][t], x, g_A2t[r][t]));
        s += ex2f(arg - m);
    }
    return LN2_F * (m + lg2f_(s));
}

// Cold A handler (provably unreachable for c>=48; kept for safety).
__device__ __noinline__ float coldA(const float4* __restrict__ X4,
                                    int tid, int c, int K) {
    float acc = 0.0f;
    for (int k = 0; k < A_ITEMS; ++k) {
        float4 xv = X4[tid + k * A_STRIDE];
        int t0 = c * 4;
        acc += robust_lp(xv.x, xv.x * xv.x, t0,     K);
        acc += robust_lp(xv.y, xv.y * xv.y, t0 + 1, K);
        acc += robust_lp(xv.z, xv.z * xv.z, t0 + 2, K);
        acc += robust_lp(xv.w, xv.w * xv.w, t0 + 3, K);
    }
    return acc - (float)(4 * A_ITEMS) * HALF_LOG_2PI;
}

// ---------------------------------------------------------------------------
// Fused main. Blocks [0,192): B path (t<192), c-coherent warps, balanced
// interleave, MUFU ex2. Blocks [192,704): A path — cp.async (LDGSTS) 8-deep
// per-thread pipeline into a 32KB smem ring: in-flight bytes live in SMEM,
// not the register file, so per-SM outstanding traffic (~200KB) far exceeds
// the bandwidth-delay product while regs stay lean. Strided coalesced layout,
// c = tid & 511 constant per thread. Deterministic fixed-order tail.
// ---------------------------------------------------------------------------
__global__ void __launch_bounds__(THREADS) k_main(const float* __restrict__ X,
                                                  float* __restrict__ out) {
    __shared__ __align__(16) char sraw[DEPTH * THREADS * 16];   /* 32KB union */
    __shared__ float  sD[R], sC[R];
    __shared__ int    sK[CSPLIT];
    __shared__ float  sred[THREADS];
    __shared__ bool   s_last;

    const float4* X4 = (const float4*)X;
    const float4* A4 = (const float4*)g_A2t;
    const int th = threadIdx.x;
    float acc = 0.0f;

    if (blockIdx.x < B_BLOCKS) {
        // ---------------- B path: t < 192 ----------------
        float4 (*sA)[CSPLIT] = (float4 (*)[CSPLIT])sraw;        /* 24.5KB */
        #pragma unroll
        for (int j = 0; j < (R * CSPLIT + THREADS - 1) / THREADS; ++j) {
            int e = th + j * THREADS;
            if (e < R * CSPLIT) {
                int r = e / CSPLIT, c = e - r * CSPLIT;
                sA[r][c] = A4[r * L4 + c];
            }
        }
        if (th < R) { sD[th] = g_D[th]; sC[th] = g_C2[th]; }
        if (th < CSPLIT) sK[th] = g_Kt4[th];
        __syncthreads();

        const int lane = th & 31;
        const int W = blockIdx.x * 8 + (th >> 5);
        const int idx = W % CSPLIT;
        const int c = (idx & 1) ? (CSPLIT - 1 - (idx >> 1)) : (idx >> 1);
        const int ng = W / CSPLIT;

        float4 xv[8];
        #pragma unroll
        for (int it = 0; it < 8; ++it) {
            int n = ng * 256 + it * 32 + lane;
            xv[it] = __ldcs(&X4[n * L4 + c]);
        }

        const int K = sK[c];
        const float t0f = (float)(4 * c);

        #pragma unroll 1
        for (int it = 0; it < 8; ++it) {
            float x0 = xv[it].x, x1 = xv[it].y, x2 = xv[it].z, x3 = xv[it].w;
            float q0 = x0 * x0, q1 = x1 * x1, q2 = x2 * x2, q3 = x3 * x3;
            float S0 = 0.f, S1 = 0.f, S2 = 0.f, S3 = 0.f;
            #pragma unroll 2
            for (int r = 0; r < K; ++r) {
                float4 ar = sA[r][c];
                float d  = sD[r];
                float cr = sC[r];
                float b0 = d * t0f, b1 = b0 + d, b2 = b1 + d, b3 = b2 + d;
                S0 += ex2f(fmaf(cr, q0, fmaf(b0, x0, ar.x)));
                S1 += ex2f(fmaf(cr, q1, fmaf(b1, x1, ar.y)));
                S2 += ex2f(fmaf(cr, q2, fmaf(b2, x2, ar.z)));
                S3 += ex2f(fmaf(cr, q3, fmaf(b3, x3, ar.w)));
            }
            float smin = fminf(fminf(S0, S1), fminf(S2, S3));
            if (smin > 1e-30f) {
                acc += LN2_F * (lg2f_(S0) + lg2f_(S1) + lg2f_(S2) + lg2f_(S3));
            } else {
                int tt = c * 4;
                acc += robust_lp(x0, q0, tt,     K);
                acc += robust_lp(x1, q1, tt + 1, K);
                acc += robust_lp(x2, q2, tt + 2, K);
                acc += robust_lp(x3, q3, tt + 3, K);
            }
            acc -= 4.0f * HALF_LOG_2PI;
        }
    } else {
        // ---------------- A path: cp.async pipelined streaming ----------------
        const float4* B4 = (const float4*)g_B2t;
        const int tid = (blockIdx.x - B_BLOCKS) * THREADS + th;   // 0..131071
        const int c = tid & (L4 - 1);
        float4 (*sbuf)[THREADS] = (float4 (*)[THREADS])sraw;

        if (c >= CSPLIT) {
            const int K = g_Kt4[c];
            if (K != 1) {
                acc = coldA(X4, tid, c, K);   // unreachable safety path
            } else {
                const float4 a = A4[c];
                const float4 b = B4[c];
                const float cc = g_C2[0];
                unsigned sb = (unsigned)__cvta_generic_to_shared(&sbuf[0][th]);
                const unsigned sstep = THREADS * 16;

                #pragma unroll
                for (int k = 0; k < DEPTH; ++k) {
                    asm volatile("cp.async.cg.shared.global [%0], [%1], 16;"
                                 :: "r"(sb + k * sstep),
                                    "l"(&X4[tid + k * A_STRIDE]) : "memory");
                    asm volatile("cp.async.commit_group;" ::: "memory");
                }

                float s = 0.0f;
                #pragma unroll 1
                for (int k = 0; k < A_ITEMS; ++k) {
                    asm volatile("cp.async.wait_group %0;" :: "n"(DEPTH - 1) : "memory");
                    float4 xv = sbuf[k & (DEPTH - 1)][th];
                    int nk = k + DEPTH;
                    if (nk < A_ITEMS) {
                        asm volatile("cp.async.cg.shared.global [%0], [%1], 16;"
                                     :: "r"(sb + (k & (DEPTH - 1)) * sstep),
                                        "l"(&X4[tid + nk * A_STRIDE]) : "memory");
                    }
                    asm volatile("cp.async.commit_group;" ::: "memory");

                    float x0 = xv.x, x1 = xv.y, x2 = xv.z, x3 = xv.w;
                    float g0 = fmaf(cc, x0 * x0, fmaf(b.x, x0, a.x));
                    float g1 = fmaf(cc, x1 * x1, fmaf(b.y, x1, a.y));
                    float g2 = fmaf(cc, x2 * x2, fmaf(b.z, x2, a.z));
                    float g3 = fmaf(cc, x3 * x3, fmaf(b.w, x3, a.w));
                    s += (g0 + g1) + (g2 + g3);
                }
                acc = LN2_F * s - (float)(4 * A_ITEMS) * HALF_LOG_2PI;
            }
        }
        __syncthreads();   // uniform per block before smem reuse in tail
    }

    // ---------------- fused deterministic tail ----------------
    sred[th] = acc;
    __syncthreads();
    for (int s = THREADS / 2; s > 0; s >>= 1) {
        if (th < s) sred[th] += sred[th + s];
        __syncthreads();
    }
    if (th == 0) {
        g_partial[blockIdx.x] = sred[0];
        __threadfence();
        unsigned n = atomicAdd(&g_count, 1u);
        s_last = (n == TOTAL_BLOCKS - 1);
    }
    __syncthreads();

    if (s_last) {
        __threadfence();
        float v = 0.0f;
        for (int idx = th; idx < TOTAL_BLOCKS; idx += THREADS)
            v += g_partial[idx];
        sred[th] = v;
        __syncthreads();
        for (int s = THREADS / 2; s > 0; s >>= 1) {
            if (th < s) sred[th] += sred[th + s];
            __syncthreads();
        }
        if (th == 0) out[0] = sred[0] / (float)NSEQ;
    }
}

// ---------------------------------------------------------------------------
extern "C" void kernel_launch(void* const* d_in, const int* in_sizes, int n_in,
                              void* d_out, int out_size) {
    const float* X       = (const float*)d_in[0];
    const float* Tr      = (const float*)d_in[1];
    const float* init_w  = (const float*)d_in[2];
    const float* sig     = (const float*)d_in[3];
    const float* mu_rate = (const float*)d_in[4];
    float* out = (float*)d_out;

    k_prep<<<128, 256>>>(Tr, init_w, sig, mu_rate);
    k_main<<<TOTAL_BLOCKS, THREADS>>>(X, out);
}